// round 15
// baseline (speedup 1.0000x reference)
#include <cuda_runtime.h>
#include <cuda_fp16.h>
#include <cstdint>

// Inputs:
//  d_in[0] pts            float32  [N_PTS, 3]
//  d_in[1] p2v_idx        int32    [N_PTS]
//  d_in[2] embeddings     float32  [N_EMB, 16]
//  d_in[3] center_points  float32  [N_VOX, 3]
//  d_in[4] center2corner  int32    [N_VOX, 8]
//  d_in[5] voxel_size     float32  [1]
// Output: float32 [N_PTS, 16]
//
// Voxel-sorted flat main: counting sort produces coalesced records
// {x,y,z,pid} in voxel order. Same-voxel quads in a warp issue identical
// emb/c2c/cp addresses in the same instruction -> coalescer merges
// (emb wavefronts 8/pt -> ~2.75/pt; emb L2 sectors 256B -> 88B/pt).
// fp16 emb table (rel_err ~2e-4 < 1e-3). 6 graph nodes.

#define N_EMB_MAX 1000000
#define N_VOX_MAX 500000
#define N_PTS_MAX 2000000
#define SBLK      1024

__device__ __align__(16) __half g_emb_h[N_EMB_MAX * 16];  // 32 MB
__device__ __align__(16) float4 g_cp4[N_VOX_MAX];         // 8 MB
__device__ int g_cnt2[2 * N_VOX_MAX];   // [0,N): hist, [N,2N): scatter cursor
__device__ int g_off[N_VOX_MAX];        // block-local exclusive scan
__device__ int g_bsum[SBLK];            // per-block sums -> exclusive scanned
__device__ __align__(16) float4 g_rec[N_PTS_MAX];  // 32 MB {x,y,z,pid}
__device__ int g_v[N_PTS_MAX];                     // 8 MB voxel per slot

// ---- cache-hint helpers ----
__device__ __forceinline__ uint64_t make_evict_last_policy() {
    uint64_t pol;
    asm("createpolicy.fractional.L2::evict_last.b64 %0, 1.0;" : "=l"(pol));
    return pol;
}
__device__ __forceinline__ uint2 ldg_last_u2(const void* p, uint64_t pol) {
    uint2 v;
    asm volatile("ld.global.nc.L2::cache_hint.v2.b32 {%0,%1}, [%2], %3;"
                 : "=r"(v.x), "=r"(v.y) : "l"(p), "l"(pol));
    return v;
}
__device__ __forceinline__ float4 ldg_last_f4(const float4* p, uint64_t pol) {
    float4 v;
    asm volatile("ld.global.nc.L2::cache_hint.v4.f32 {%0,%1,%2,%3}, [%4], %5;"
                 : "=f"(v.x), "=f"(v.y), "=f"(v.z), "=f"(v.w)
                 : "l"(p), "l"(pol));
    return v;
}
__device__ __forceinline__ void ldg_last_i8(const int* p, int* o) {
    asm volatile("ld.global.nc.L2::evict_last.v8.b32 "
                 "{%0,%1,%2,%3,%4,%5,%6,%7}, [%8];"
                 : "=r"(o[0]), "=r"(o[1]), "=r"(o[2]), "=r"(o[3]),
                   "=r"(o[4]), "=r"(o[5]), "=r"(o[6]), "=r"(o[7])
                 : "l"(p));
}
__device__ __forceinline__ float4 ldg_stream_f4(const float4* p) {
    float4 v;
    asm volatile("ld.global.cs.v4.f32 {%0,%1,%2,%3}, [%4];"
                 : "=f"(v.x), "=f"(v.y), "=f"(v.z), "=f"(v.w) : "l"(p));
    return v;
}
__device__ __forceinline__ float ldg_stream_f(const float* p) {
    float v;
    asm volatile("ld.global.cs.f32 %0, [%1];" : "=f"(v) : "l"(p));
    return v;
}
__device__ __forceinline__ int ldg_stream_i(const int* p) {
    int v;
    asm volatile("ld.global.cs.s32 %0, [%1];" : "=r"(v) : "l"(p));
    return v;
}
__device__ __forceinline__ void stg_last_u4(void* p, uint4 v, uint64_t pol) {
    asm volatile("st.global.L2::cache_hint.v4.b32 [%0], {%1,%2,%3,%4}, %5;"
                 :: "l"(p), "r"(v.x), "r"(v.y), "r"(v.z), "r"(v.w), "l"(pol));
}
__device__ __forceinline__ void stg_last_f4(float4* p, float4 v, uint64_t pol) {
    asm volatile("st.global.L2::cache_hint.v4.f32 [%0], {%1,%2,%3,%4}, %5;"
                 :: "l"(p), "f"(v.x), "f"(v.y), "f"(v.z), "f"(v.w), "l"(pol));
}
__device__ __forceinline__ void stg_stream_f4(float4* p, float4 v) {
    asm volatile("st.global.cs.v4.f32 [%0], {%1,%2,%3,%4};"
                 :: "l"(p), "f"(v.x), "f"(v.y), "f"(v.z), "f"(v.w));
}

// ---- k1: prep: emb fp32->fp16, cp->float4, histogram of p2v ----
__global__ void prep_kernel(const float* __restrict__ emb,
                            const float* __restrict__ cp,
                            const int*   __restrict__ p2v,
                            int n8, int n_vox, int n_pts)
{
    int i = blockIdx.x * blockDim.x + threadIdx.x;
    uint64_t pol = make_evict_last_policy();
    if (i < n8) {
        const float4* src = reinterpret_cast<const float4*>(emb) + (size_t)i * 2;
        float4 a = ldg_stream_f4(&src[0]);
        float4 b = ldg_stream_f4(&src[1]);
        __half2 h0 = __floats2half2_rn(a.x, a.y);
        __half2 h1 = __floats2half2_rn(a.z, a.w);
        __half2 h2 = __floats2half2_rn(b.x, b.y);
        __half2 h3 = __floats2half2_rn(b.z, b.w);
        uint4 packed;
        packed.x = *reinterpret_cast<uint32_t*>(&h0);
        packed.y = *reinterpret_cast<uint32_t*>(&h1);
        packed.z = *reinterpret_cast<uint32_t*>(&h2);
        packed.w = *reinterpret_cast<uint32_t*>(&h3);
        stg_last_u4(reinterpret_cast<uint4*>(g_emb_h) + i, packed, pol);
        return;
    }
    int j = i - n8;
    if (j < n_vox) {
        float x = ldg_stream_f(&cp[3 * j + 0]);
        float y = ldg_stream_f(&cp[3 * j + 1]);
        float z = ldg_stream_f(&cp[3 * j + 2]);
        stg_last_f4(&g_cp4[j], make_float4(x, y, z, 0.0f), pol);
        return;
    }
    int k = j - n_vox;
    if (k < n_pts) {
        atomicAdd(&g_cnt2[ldg_stream_i(&p2v[k])], 1);
    }
}

// ---- k2: per-block exclusive scan of hist (shuffle-based) ----
__global__ void scan_block_kernel(int n)
{
    __shared__ int wsum[SBLK / 32];
    int t = threadIdx.x;
    int g = blockIdx.x * SBLK + t;
    int lane = t & 31, wid = t >> 5;
    int x = (g < n) ? g_cnt2[g] : 0;
    int v = x;
    #pragma unroll
    for (int o = 1; o < 32; o <<= 1) {
        int y = __shfl_up_sync(0xffffffffu, v, o);
        if (lane >= o) v += y;
    }
    if (lane == 31) wsum[wid] = v;
    __syncthreads();
    if (wid == 0) {
        int s = (lane < SBLK / 32) ? wsum[lane] : 0;
        #pragma unroll
        for (int o = 1; o < 32; o <<= 1) {
            int y = __shfl_up_sync(0xffffffffu, s, o);
            if (lane >= o) s += y;
        }
        if (lane < SBLK / 32) wsum[lane] = s;
    }
    __syncthreads();
    int excl = v - x + (wid > 0 ? wsum[wid - 1] : 0);
    if (g < n) g_off[g] = excl;
    if (t == SBLK - 1) g_bsum[blockIdx.x] = excl + x;
}

// ---- k3: exclusive scan of block sums in place (1 block) ----
__global__ void scan_top_kernel(int nb)
{
    __shared__ int wsum[SBLK / 32];
    int t = threadIdx.x;
    int lane = t & 31, wid = t >> 5;
    int x = (t < nb) ? g_bsum[t] : 0;
    int v = x;
    #pragma unroll
    for (int o = 1; o < 32; o <<= 1) {
        int y = __shfl_up_sync(0xffffffffu, v, o);
        if (lane >= o) v += y;
    }
    if (lane == 31) wsum[wid] = v;
    __syncthreads();
    if (wid == 0) {
        int s = (lane < SBLK / 32) ? wsum[lane] : 0;
        #pragma unroll
        for (int o = 1; o < 32; o <<= 1) {
            int y = __shfl_up_sync(0xffffffffu, s, o);
            if (lane >= o) s += y;
        }
        if (lane < SBLK / 32) wsum[lane] = s;
    }
    __syncthreads();
    if (t < nb) g_bsum[t] = v - x + (wid > 0 ? wsum[wid - 1] : 0);
}

// ---- k4: scatter coalesced records into voxel order ----
__global__ void scatter_kernel(const int*   __restrict__ p2v,
                               const float* __restrict__ pts,
                               int n_pts)
{
    int i = blockIdx.x * blockDim.x + threadIdx.x;
    if (i >= n_pts) return;
    int v = ldg_stream_i(&p2v[i]);
    float x = ldg_stream_f(&pts[3 * i + 0]);
    float y = ldg_stream_f(&pts[3 * i + 1]);
    float z = ldg_stream_f(&pts[3 * i + 2]);
    int base = __ldg(&g_off[v]) + __ldg(&g_bsum[v >> 10]);
    int pos  = base + atomicAdd(&g_cnt2[N_VOX_MAX + v], 1);
    g_rec[pos] = make_float4(x, y, z, __int_as_float(i));
    g_v[pos] = v;
}

// ---- k5: main — quad per sorted record (uniform flow, warp dedup) ----
__global__ void voxel_interp_sorted_kernel(
    const int*    __restrict__ center2corner,
    const float*  __restrict__ voxel_size,
    float*        __restrict__ out,
    int n_pts)
{
    int tid = blockIdx.x * blockDim.x + threadIdx.x;
    int i   = tid >> 2;
    int sub = tid & 3;
    if (i >= n_pts) return;

    uint64_t pol = make_evict_last_policy();

    // coalesced: warp reads 8 recs = 128B (1 line) + 8 ints (1 sector)
    float4 rec = __ldg(&g_rec[i]);
    int v = __ldg(&g_v[i]);

    // same-voxel quads (~2.75 distinct voxels/warp) merge in these loads
    int cidx[8];
    ldg_last_i8(center2corner + (size_t)v * 8, cidx);
    float4 cp = ldg_last_f4(&g_cp4[v], pol);

    uint2 r[8];
    #pragma unroll
    for (int c = 0; c < 8; ++c) {
        const char* rowp = reinterpret_cast<const char*>(g_emb_h)
                         + (size_t)cidx[c] * 32 + sub * 8;
        r[c] = ldg_last_u2(rowp, pol);
    }

    float inv_vs = 1.0f / __ldg(&voxel_size[0]);
    float px = (rec.x - cp.x) * inv_vs + 0.5f;
    float py = (rec.y - cp.y) * inv_vs + 0.5f;
    float pz = (rec.z - cp.z) * inv_vs + 0.5f;

    // corner c (meshgrid ij): bit2 -> x, bit1 -> y, bit0 -> z
    float wx[2] = {1.0f - px, px};
    float wy[2] = {1.0f - py, py};
    float wz[2] = {1.0f - pz, pz};

    float4 acc = make_float4(0.0f, 0.0f, 0.0f, 0.0f);
    #pragma unroll
    for (int c = 0; c < 8; ++c) {
        float w = wx[(c >> 2) & 1] * wy[(c >> 1) & 1] * wz[c & 1];
        float2 f01 = __half22float2(*reinterpret_cast<const __half2*>(&r[c].x));
        float2 f23 = __half22float2(*reinterpret_cast<const __half2*>(&r[c].y));
        acc.x = fmaf(w, f01.x, acc.x);
        acc.y = fmaf(w, f01.y, acc.y);
        acc.z = fmaf(w, f23.x, acc.z);
        acc.w = fmaf(w, f23.y, acc.w);
    }

    int pid = __float_as_int(rec.w);
    stg_stream_f4(reinterpret_cast<float4*>(out) + (size_t)pid * 4 + sub, acc);
}

extern "C" void kernel_launch(void* const* d_in, const int* in_sizes, int n_in,
                              void* d_out, int out_size)
{
    const float* pts            = (const float*)d_in[0];
    const int*   p2v_idx        = (const int*)  d_in[1];
    const float* embeddings     = (const float*)d_in[2];
    const float* center_points  = (const float*)d_in[3];
    const int*   center2corner  = (const int*)  d_in[4];
    const float* voxel_size     = (const float*)d_in[5];
    float*       out            = (float*)d_out;

    int n8    = in_sizes[2] / 8;
    int n_vox = in_sizes[3] / 3;
    int n_pts = in_sizes[0] / 3;

    // node 1: zero hist + cursors (one symbol, one memset)
    void* cnt_ptr = nullptr;
    cudaGetSymbolAddress(&cnt_ptr, g_cnt2);
    cudaMemsetAsync(cnt_ptr, 0, 2 * (size_t)N_VOX_MAX * sizeof(int));

    // node 2: tables + histogram
    int prep_threads = n8 + n_vox + n_pts;
    prep_kernel<<<(prep_threads + 255) / 256, 256>>>(
        embeddings, center_points, p2v_idx, n8, n_vox, n_pts);

    // nodes 3-4: scan
    int nblocks = (n_vox + SBLK - 1) / SBLK;   // 489
    scan_block_kernel<<<nblocks, SBLK>>>(n_vox);
    scan_top_kernel<<<1, SBLK>>>(nblocks);

    // node 5: scatter coalesced records
    scatter_kernel<<<(n_pts + 255) / 256, 256>>>(p2v_idx, pts, n_pts);

    // node 6: main
    int total_threads = n_pts * 4;
    voxel_interp_sorted_kernel<<<(total_threads + 255) / 256, 256>>>(
        center2corner, voxel_size, out, n_pts);
}

// round 16
// speedup vs baseline: 1.5907x; 1.5907x over previous
#include <cuda_runtime.h>
#include <cuda_fp16.h>
#include <cstdint>

// Inputs:
//  d_in[0] pts            float32  [N_PTS, 3]
//  d_in[1] p2v_idx        int32    [N_PTS]
//  d_in[2] embeddings     float32  [N_EMB, 16]
//  d_in[3] center_points  float32  [N_VOX, 3]
//  d_in[4] center2corner  int32    [N_VOX, 8]
//  d_in[5] voxel_size     float32  [1]
// Output: float32 [N_PTS, 16]
//
// Final configuration (best measured: 104.9us total, main 92.7us).
// fp16 embedding table (halves gather bytes; rel_err ~2e-4 < 1e-3 threshold),
// float4-padded center_points, 256-bit c2c load, batched 8-row gather (MLP~8),
// evict_last on gathered tables, streaming hints on pass-through data.
// Main kernel is at its L1-wavefront floor (~11 wf/pt, 8 of which are the
// irreducible random embedding-row gather); verified against sort/group/PDL/
// shuffle alternatives across R7-R15, all of which regressed.

#define N_EMB_MAX 1000000
#define N_VOX_MAX 500000
__device__ __align__(16) __half g_emb_h[N_EMB_MAX * 16];  // 32 MB
__device__ __align__(16) float4 g_cp4[N_VOX_MAX];         // 8 MB

// ---- cache-hint helpers ----
__device__ __forceinline__ uint64_t make_evict_last_policy() {
    uint64_t pol;
    asm("createpolicy.fractional.L2::evict_last.b64 %0, 1.0;" : "=l"(pol));
    return pol;
}
__device__ __forceinline__ uint2 ldg_last_u2(const void* p, uint64_t pol) {
    uint2 v;
    asm volatile("ld.global.nc.L2::cache_hint.v2.b32 {%0,%1}, [%2], %3;"
                 : "=r"(v.x), "=r"(v.y) : "l"(p), "l"(pol));
    return v;
}
__device__ __forceinline__ float4 ldg_last_f4(const float4* p, uint64_t pol) {
    float4 v;
    asm volatile("ld.global.nc.L2::cache_hint.v4.f32 {%0,%1,%2,%3}, [%4], %5;"
                 : "=f"(v.x), "=f"(v.y), "=f"(v.z), "=f"(v.w)
                 : "l"(p), "l"(pol));
    return v;
}
__device__ __forceinline__ void ldg_last_i8(const int* p, int* o) {
    asm volatile("ld.global.nc.L2::evict_last.v8.b32 "
                 "{%0,%1,%2,%3,%4,%5,%6,%7}, [%8];"
                 : "=r"(o[0]), "=r"(o[1]), "=r"(o[2]), "=r"(o[3]),
                   "=r"(o[4]), "=r"(o[5]), "=r"(o[6]), "=r"(o[7])
                 : "l"(p));
}
__device__ __forceinline__ float4 ldg_stream_f4(const float4* p) {
    float4 v;
    asm volatile("ld.global.cs.v4.f32 {%0,%1,%2,%3}, [%4];"
                 : "=f"(v.x), "=f"(v.y), "=f"(v.z), "=f"(v.w) : "l"(p));
    return v;
}
__device__ __forceinline__ float ldg_stream_f(const float* p) {
    float v;
    asm volatile("ld.global.cs.f32 %0, [%1];" : "=f"(v) : "l"(p));
    return v;
}
__device__ __forceinline__ int ldg_stream_i(const int* p) {
    int v;
    asm volatile("ld.global.cs.s32 %0, [%1];" : "=r"(v) : "l"(p));
    return v;
}
__device__ __forceinline__ void stg_last_u4(void* p, uint4 v, uint64_t pol) {
    asm volatile("st.global.L2::cache_hint.v4.b32 [%0], {%1,%2,%3,%4}, %5;"
                 :: "l"(p), "r"(v.x), "r"(v.y), "r"(v.z), "r"(v.w), "l"(pol));
}
__device__ __forceinline__ void stg_last_f4(float4* p, float4 v, uint64_t pol) {
    asm volatile("st.global.L2::cache_hint.v4.f32 [%0], {%1,%2,%3,%4}, %5;"
                 :: "l"(p), "f"(v.x), "f"(v.y), "f"(v.z), "f"(v.w), "l"(pol));
}
__device__ __forceinline__ void stg_stream_f4(float4* p, float4 v) {
    asm volatile("st.global.cs.v4.f32 [%0], {%1,%2,%3,%4};"
                 :: "l"(p), "f"(v.x), "f"(v.y), "f"(v.z), "f"(v.w));
}

// ---- k1: table prep: emb fp32->fp16 (8 floats/thread), cp->float4 ----
__global__ void prep_kernel(const float* __restrict__ emb,
                            const float* __restrict__ cp,
                            int n8, int n_vox)
{
    int i = blockIdx.x * blockDim.x + threadIdx.x;
    uint64_t pol = make_evict_last_policy();
    if (i < n8) {
        const float4* src = reinterpret_cast<const float4*>(emb) + (size_t)i * 2;
        float4 a = ldg_stream_f4(&src[0]);
        float4 b = ldg_stream_f4(&src[1]);
        __half2 h0 = __floats2half2_rn(a.x, a.y);
        __half2 h1 = __floats2half2_rn(a.z, a.w);
        __half2 h2 = __floats2half2_rn(b.x, b.y);
        __half2 h3 = __floats2half2_rn(b.z, b.w);
        uint4 packed;
        packed.x = *reinterpret_cast<uint32_t*>(&h0);
        packed.y = *reinterpret_cast<uint32_t*>(&h1);
        packed.z = *reinterpret_cast<uint32_t*>(&h2);
        packed.w = *reinterpret_cast<uint32_t*>(&h3);
        stg_last_u4(reinterpret_cast<uint4*>(g_emb_h) + i, packed, pol);
        return;
    }
    int j = i - n8;
    if (j < n_vox) {
        float x = ldg_stream_f(&cp[3 * j + 0]);
        float y = ldg_stream_f(&cp[3 * j + 1]);
        float z = ldg_stream_f(&cp[3 * j + 2]);
        stg_last_f4(&g_cp4[j], make_float4(x, y, z, 0.0f), pol);
    }
}

// ---- k2: main — 4 threads per point, each owns 4 of 16 dims ----
__global__ void __launch_bounds__(256) voxel_interp_kernel(
    const float*  __restrict__ pts,
    const int*    __restrict__ p2v_idx,
    const int*    __restrict__ center2corner,
    const float*  __restrict__ voxel_size,
    float*        __restrict__ out,
    int n_pts)
{
    int tid   = blockIdx.x * blockDim.x + threadIdx.x;
    int point = tid >> 2;
    int sub   = tid & 3;
    if (point >= n_pts) return;

    uint64_t pol = make_evict_last_policy();

    int v = ldg_stream_i(&p2v_idx[point]);

    // gather all indices first (max MLP)
    int cidx[8];
    ldg_last_i8(center2corner + (size_t)v * 8, cidx);
    float4 cp = ldg_last_f4(&g_cp4[v], pol);

    float inv_vs = 1.0f / __ldg(&voxel_size[0]);
    float px = (ldg_stream_f(&pts[3 * point + 0]) - cp.x) * inv_vs + 0.5f;
    float py = (ldg_stream_f(&pts[3 * point + 1]) - cp.y) * inv_vs + 0.5f;
    float pz = (ldg_stream_f(&pts[3 * point + 2]) - cp.z) * inv_vs + 0.5f;

    // batch all 8 embedding gathers before any FMA (MLP ~8)
    uint2 r[8];
    #pragma unroll
    for (int c = 0; c < 8; ++c) {
        const char* rowp = reinterpret_cast<const char*>(g_emb_h)
                         + (size_t)cidx[c] * 32 + sub * 8;
        r[c] = ldg_last_u2(rowp, pol);
    }

    // corner c (meshgrid ij): bit2 -> x, bit1 -> y, bit0 -> z
    float wx[2] = {1.0f - px, px};
    float wy[2] = {1.0f - py, py};
    float wz[2] = {1.0f - pz, pz};

    float4 acc = make_float4(0.0f, 0.0f, 0.0f, 0.0f);
    #pragma unroll
    for (int c = 0; c < 8; ++c) {
        float w = wx[(c >> 2) & 1] * wy[(c >> 1) & 1] * wz[c & 1];
        float2 f01 = __half22float2(*reinterpret_cast<const __half2*>(&r[c].x));
        float2 f23 = __half22float2(*reinterpret_cast<const __half2*>(&r[c].y));
        acc.x = fmaf(w, f01.x, acc.x);
        acc.y = fmaf(w, f01.y, acc.y);
        acc.z = fmaf(w, f23.x, acc.z);
        acc.w = fmaf(w, f23.y, acc.w);
    }

    stg_stream_f4(reinterpret_cast<float4*>(out) + (size_t)point * 4 + sub, acc);
}

extern "C" void kernel_launch(void* const* d_in, const int* in_sizes, int n_in,
                              void* d_out, int out_size)
{
    const float* pts            = (const float*)d_in[0];
    const int*   p2v_idx        = (const int*)  d_in[1];
    const float* embeddings     = (const float*)d_in[2];
    const float* center_points  = (const float*)d_in[3];
    const int*   center2corner  = (const int*)  d_in[4];
    const float* voxel_size     = (const float*)d_in[5];
    float*       out            = (float*)d_out;

    int n8    = in_sizes[2] / 8;   // emb chunks of 8 floats
    int n_vox = in_sizes[3] / 3;
    int n_pts = in_sizes[0] / 3;

    int prep_threads = n8 + n_vox;
    prep_kernel<<<(prep_threads + 255) / 256, 256>>>(
        embeddings, center_points, n8, n_vox);

    int total_threads = n_pts * 4;
    voxel_interp_kernel<<<(total_threads + 255) / 256, 256>>>(
        pts, p2v_idx, center2corner, voxel_size, out, n_pts);
}